// round 8
// baseline (speedup 1.0000x reference)
#include <cuda_runtime.h>
#include <cstdint>

// Problem constants (fixed by the reference)
#define BATCH   4096
#define IN_DIM  512
#define OUT_DIM 512
#define NH      32
#define KC      64            // K-chunk = one input dim: 32 harmonics x {cos,sin}

#define M_TILE  64
#define N_TILE  128
#define THREADS 256

// ---------- packed fp32x2 helpers (FFMA2 path: ptxas never emits these from C++) ----------
__device__ __forceinline__ unsigned long long ffma2(unsigned long long a,
                                                    unsigned long long b,
                                                    unsigned long long c) {
    unsigned long long d;
    asm("fma.rn.f32x2 %0, %1, %2, %3;" : "=l"(d) : "l"(a), "l"(b), "l"(c));
    return d;
}
__device__ __forceinline__ unsigned long long splat2(float a) {
    unsigned long long d;
    asm("mov.b64 %0, {%1, %1};" : "=l"(d) : "f"(a));
    return d;
}
__device__ __forceinline__ float2 unpack2(unsigned long long v) {
    float2 r;
    asm("mov.b64 {%0, %1}, %2;" : "=f"(r.x), "=f"(r.y) : "l"(v));
    return r;
}
__device__ __forceinline__ void cp_async16(uint32_t dst_smem, const void* src) {
    asm volatile("cp.async.cg.shared.global [%0], [%1], 16;" :: "r"(dst_smem), "l"(src) : "memory");
}

__global__ void __launch_bounds__(THREADS, 2)
fourier_kan_kernel(const float* __restrict__ x,
                   const float* __restrict__ fc,     // [IN_DIM,NH,2,OUT_DIM] == [K=32768, N=512] row-major
                   const float* __restrict__ bias,
                   float*       __restrict__ out)
{
    __shared__ float As[KC * M_TILE];   // [k][m]  16 KB
    __shared__ float Bs[KC * N_TILE];   // [k][n]  32 KB   (total = 48 KB static, 2 CTA/SM)

    const int tid = threadIdx.x;
    const int tx  = tid & 15;           // 0..15 -> 8 output cols each
    const int ty  = tid >> 4;           // 0..15 -> 4 batch rows each
    const int n0  = blockIdx.x * N_TILE;
    const int m0  = blockIdx.y * M_TILE;

    // W-tile cooperative load mapping: 2048 float4 per chunk, 8 per thread
    const int wwid  = tid >> 5;         // 0..7
    const int wlane = tid & 31;         // 0..31 -> float4 column
    const uint32_t bs_base =
        (uint32_t)__cvta_generic_to_shared(Bs) + (uint32_t)((wwid * N_TILE + wlane * 4) * 4);

    unsigned long long acc[4][4];
    #pragma unroll
    for (int i = 0; i < 4; ++i)
        #pragma unroll
        for (int j = 0; j < 4; ++j) acc[i][j] = 0ull;

    // bias for this thread's 8 output columns
    float bias_r[8];
    #pragma unroll
    for (int j = 0; j < 8; ++j) bias_r[j] = bias[n0 + tx * 8 + j];

    // x row for trig-generating threads (tid < 64): one float per chunk
    const float* xp = x + (size_t)(m0 + (tid < M_TILE ? tid : 0)) * IN_DIM;

    for (int ci = 0; ci < IN_DIM; ++ci) {
        __syncthreads();   // previous chunk's compute done before smem overwrite

        // --- async load of W chunk: rows [ci*64, ci*64+64), cols [n0, n0+128) ---
        const float* src = fc + ((size_t)ci * KC + wwid) * OUT_DIM + n0 + wlane * 4;
        #pragma unroll
        for (int j = 0; j < 8; ++j) {
            cp_async16(bs_base + (uint32_t)(j * 8 * N_TILE * 4),
                       src + (size_t)j * 8 * OUT_DIM);
        }
        asm volatile("cp.async.commit_group;" ::: "memory");

        // --- generate trig features for this input dim (warps 0-1), overlapped with TMA-less cp.async ---
        if (tid < M_TILE) {
            const float xv = xp[ci];
            float s1, c1;
            sincosf(xv, &s1, &c1);          // harmonic k=1; |xv| small -> accurate even w/ fast math
            float c = c1, s = s1;
            #pragma unroll
            for (int g = 0; g < NH; ++g) {  // rotation recurrence: cos/sin((g+1)x)
                As[(2 * g)     * M_TILE + tid] = c;
                As[(2 * g + 1) * M_TILE + tid] = s;
                const float cn = __fmaf_rn(c, c1, -s * s1);
                const float sn = __fmaf_rn(s, c1,  c * s1);
                c = cn; s = sn;
            }
        }

        asm volatile("cp.async.wait_group 0;" ::: "memory");
        __syncthreads();

        // --- main FFMA2 loop: 64 k-steps, 16 FFMA2 (=32 FMA) per thread per step ---
        #pragma unroll 8
        for (int k = 0; k < KC; ++k) {
            const float4 a4 = *reinterpret_cast<const float4*>(&As[k * M_TILE + ty * 4]);
            const unsigned long long* bp =
                reinterpret_cast<const unsigned long long*>(&Bs[k * N_TILE + tx * 8]);
            unsigned long long bq[4];
            bq[0] = bp[0]; bq[1] = bp[1]; bq[2] = bp[2]; bq[3] = bp[3];
            unsigned long long aq[4];
            aq[0] = splat2(a4.x); aq[1] = splat2(a4.y);
            aq[2] = splat2(a4.z); aq[3] = splat2(a4.w);
            #pragma unroll
            for (int mi = 0; mi < 4; ++mi)
                #pragma unroll
                for (int nj = 0; nj < 4; ++nj)
                    acc[mi][nj] = ffma2(aq[mi], bq[nj], acc[mi][nj]);
        }
    }

    // --- epilogue: add bias, store 4 rows x 8 cols as 2x float4 per row ---
    #pragma unroll
    for (int mi = 0; mi < 4; ++mi) {
        const int m = m0 + ty * 4 + mi;
        float* op = out + (size_t)m * OUT_DIM + n0 + tx * 8;
        float2 v0 = unpack2(acc[mi][0]);
        float2 v1 = unpack2(acc[mi][1]);
        float2 v2 = unpack2(acc[mi][2]);
        float2 v3 = unpack2(acc[mi][3]);
        float4 o0, o1;
        o0.x = v0.x + bias_r[0]; o0.y = v0.y + bias_r[1];
        o0.z = v1.x + bias_r[2]; o0.w = v1.y + bias_r[3];
        o1.x = v2.x + bias_r[4]; o1.y = v2.y + bias_r[5];
        o1.z = v3.x + bias_r[6]; o1.w = v3.y + bias_r[7];
        *reinterpret_cast<float4*>(op)     = o0;
        *reinterpret_cast<float4*>(op + 4) = o1;
    }
}

extern "C" void kernel_launch(void* const* d_in, const int* in_sizes, int n_in,
                              void* d_out, int out_size) {
    const float* x    = (const float*)d_in[0];   // [4096, 512]
    const float* fc   = (const float*)d_in[1];   // [512, 32, 2, 512]
    const float* bias = (const float*)d_in[2];   // [512]
    float* out        = (float*)d_out;           // [4096, 512]

    dim3 grid(OUT_DIM / N_TILE, BATCH / M_TILE); // (4, 64) = 256 CTAs
    fourier_kan_kernel<<<grid, THREADS>>>(x, fc, bias, out);
}

// round 10
// speedup vs baseline: 1.1741x; 1.1741x over previous
#include <cuda_runtime.h>
#include <cstdint>

// Problem constants (fixed by the reference)
#define BATCH   4096
#define IN_DIM  512
#define OUT_DIM 512
#define NH      32
#define KC      64            // K-chunk = one input dim: 32 harmonics x {cos,sin}

#define M_TILE  64
#define N_TILE  128
#define THREADS 256
#define CHUNK_FLOATS (KC * N_TILE)        // 8192 floats = 32 KB per buffer

typedef unsigned long long ull;

// ---------- packed fp32x2 helpers (FFMA2: ptxas never emits these from C++) ----------
__device__ __forceinline__ ull ffma2(ull a, ull b, ull c) {
    ull d;
    asm("fma.rn.f32x2 %0, %1, %2, %3;" : "=l"(d) : "l"(a), "l"(b), "l"(c));
    return d;
}
__device__ __forceinline__ ull splat2(float a) {
    ull d;
    asm("mov.b64 %0, {%1, %1};" : "=l"(d) : "f"(a));
    return d;
}
__device__ __forceinline__ float2 unpack2(ull v) {
    float2 r;
    asm("mov.b64 {%0, %1}, %2;" : "=f"(r.x), "=f"(r.y) : "l"(v));
    return r;
}
__device__ __forceinline__ void cp_async16(uint32_t dst_smem, const void* src) {
    asm volatile("cp.async.cg.shared.global [%0], [%1], 16;" :: "r"(dst_smem), "l"(src) : "memory");
}

__global__ void __launch_bounds__(THREADS, 2)
fourier_kan_kernel(const float* __restrict__ x,
                   const float* __restrict__ fc,   // [IN_DIM,NH,2,OUT_DIM] == [K=32768,N=512]
                   const float* __restrict__ bias,
                   float*       __restrict__ out)
{
    extern __shared__ float Bs[];       // [2][KC][N_TILE]  = 64 KB dynamic

    const int tid = threadIdx.x;
    const int tx  = tid & 15;           // 0..15 -> 8 output cols each
    const int ty  = tid >> 4;           // 0..15 -> 4 batch rows each
    const int n0  = blockIdx.x * N_TILE;
    const int m0  = blockIdx.y * M_TILE;

    // cp.async cooperative mapping: 2048 float4 per chunk, 8 per thread
    const int wwid  = tid >> 5;         // 0..7  -> base k-row
    const int wlane = tid & 31;         // 0..31 -> float4 column
    const uint32_t st_base =
        (uint32_t)__cvta_generic_to_shared(Bs) + (uint32_t)((wwid * N_TILE + wlane * 4) * 4);

    ull acc[4][4];
    #pragma unroll
    for (int i = 0; i < 4; ++i)
        #pragma unroll
        for (int j = 0; j < 4; ++j) acc[i][j] = 0ull;

    const float* xbase = x + (size_t)(m0 + ty * 4) * IN_DIM;

    // ---- prologue: async-load chunk 0 into buffer 0 ----
    {
        const float* src = fc + (size_t)wwid * OUT_DIM + n0 + wlane * 4;
        #pragma unroll
        for (int j = 0; j < 8; ++j)
            cp_async16(st_base + (uint32_t)(j * 8 * N_TILE * 4), src + (size_t)j * 8 * OUT_DIM);
        asm volatile("cp.async.commit_group;" ::: "memory");
    }

    for (int ci = 0; ci < IN_DIM; ++ci) {
        const int buf = ci & 1;

        // x values for this thread's 4 rows (issue early; L1-resident lines)
        float xv[4];
        #pragma unroll
        for (int r = 0; r < 4; ++r) xv[r] = __ldg(&xbase[(size_t)r * IN_DIM + ci]);

        __syncthreads();   // everyone done reading buf^1 before we overwrite it

        if (ci + 1 < IN_DIM) {
            const float* src = fc + ((size_t)(ci + 1) * KC + wwid) * OUT_DIM + n0 + wlane * 4;
            const uint32_t dst = st_base + (uint32_t)((buf ^ 1) * CHUNK_FLOATS * 4);
            #pragma unroll
            for (int j = 0; j < 8; ++j)
                cp_async16(dst + (uint32_t)(j * 8 * N_TILE * 4), src + (size_t)j * 8 * OUT_DIM);
            asm volatile("cp.async.commit_group;" ::: "memory");
            asm volatile("cp.async.wait_group 1;" ::: "memory");   // chunk ci is ready
        } else {
            asm volatile("cp.async.wait_group 0;" ::: "memory");
        }

        // trig seeds: harmonic 1 via __sincosf, harmonic 2 via double angle
        float ca[4], sa[4], cb[4], sb[4], tt[4];
        #pragma unroll
        for (int r = 0; r < 4; ++r) {
            __sincosf(xv[r], &sa[r], &ca[r]);
            tt[r] = 2.0f * ca[r];
            cb[r] = __fmaf_rn(tt[r], ca[r], -1.0f);   // cos 2x
            sb[r] = tt[r] * sa[r];                    // sin 2x
        }

        __syncthreads();   // chunk ci visible to all threads

        const float* B0 = Bs + buf * CHUNK_FLOATS + tx * 8;

        // one k-step: 4 LDS.64 + 4 splats + 16 FFMA2
        #define KSTEP(krow, av)                                                        \
        {                                                                              \
            const ull* bp = reinterpret_cast<const ull*>(B0 + (krow) * N_TILE);        \
            ull bq0 = bp[0], bq1 = bp[1], bq2 = bp[2], bq3 = bp[3];                    \
            _Pragma("unroll")                                                          \
            for (int r = 0; r < 4; ++r) {                                              \
                ull aq = splat2((av)[r]);                                              \
                acc[r][0] = ffma2(aq, bq0, acc[r][0]);                                 \
                acc[r][1] = ffma2(aq, bq1, acc[r][1]);                                 \
                acc[r][2] = ffma2(aq, bq2, acc[r][2]);                                 \
                acc[r][3] = ffma2(aq, bq3, acc[r][3]);                                 \
            }                                                                          \
        }

        #pragma unroll
        for (int g = 0; g < NH; g += 2) {
            if (g) {   // advance a := harmonic g+1 (Chebyshev; neg folds into FFMA)
                #pragma unroll
                for (int r = 0; r < 4; ++r) {
                    ca[r] = __fmaf_rn(tt[r], cb[r], -ca[r]);
                    sa[r] = __fmaf_rn(tt[r], sb[r], -sa[r]);
                }
            }
            KSTEP(2 * g,     ca)   // cos((g+1)x)
            KSTEP(2 * g + 1, sa)   // sin((g+1)x)
            if (g) {   // advance b := harmonic g+2
                #pragma unroll
                for (int r = 0; r < 4; ++r) {
                    cb[r] = __fmaf_rn(tt[r], ca[r], -cb[r]);
                    sb[r] = __fmaf_rn(tt[r], sa[r], -sb[r]);
                }
            }
            KSTEP(2 * g + 2, cb)   // cos((g+2)x)
            KSTEP(2 * g + 3, sb)   // sin((g+2)x)
        }
        #undef KSTEP
    }

    // ---- epilogue: add bias, store 4 rows x 8 cols as 2x float4 per row ----
    float bias_r[8];
    #pragma unroll
    for (int j = 0; j < 8; ++j) bias_r[j] = bias[n0 + tx * 8 + j];

    #pragma unroll
    for (int mi = 0; mi < 4; ++mi) {
        const int m = m0 + ty * 4 + mi;
        float* op = out + (size_t)m * OUT_DIM + n0 + tx * 8;
        float2 v0 = unpack2(acc[mi][0]);
        float2 v1 = unpack2(acc[mi][1]);
        float2 v2 = unpack2(acc[mi][2]);
        float2 v3 = unpack2(acc[mi][3]);
        float4 o0, o1;
        o0.x = v0.x + bias_r[0]; o0.y = v0.y + bias_r[1];
        o0.z = v1.x + bias_r[2]; o0.w = v1.y + bias_r[3];
        o1.x = v2.x + bias_r[4]; o1.y = v2.y + bias_r[5];
        o1.z = v3.x + bias_r[6]; o1.w = v3.y + bias_r[7];
        *reinterpret_cast<float4*>(op)     = o0;
        *reinterpret_cast<float4*>(op + 4) = o1;
    }
}

extern "C" void kernel_launch(void* const* d_in, const int* in_sizes, int n_in,
                              void* d_out, int out_size) {
    const float* x    = (const float*)d_in[0];   // [4096, 512]
    const float* fc   = (const float*)d_in[1];   // [512, 32, 2, 512]
    const float* bias = (const float*)d_in[2];   // [512]
    float* out        = (float*)d_out;           // [4096, 512]

    const int smem = 2 * CHUNK_FLOATS * sizeof(float);   // 64 KB
    cudaFuncSetAttribute(fourier_kan_kernel,
                         cudaFuncAttributeMaxDynamicSharedMemorySize, smem);

    dim3 grid(OUT_DIM / N_TILE, BATCH / M_TILE);         // (4, 64) = 256 CTAs
    fourier_kan_kernel<<<grid, THREADS, smem>>>(x, fc, bias, out);
}

// round 11
// speedup vs baseline: 1.6609x; 1.4146x over previous
#include <cuda_runtime.h>
#include <cstdint>

// Problem constants (fixed by the reference)
#define BATCH   4096
#define IN_DIM  512
#define OUT_DIM 512
#define NH      32
#define KC      64            // K-chunk = one input dim: 32 harmonics x {cos,sin}

#define M_TILE  64
#define N_TILE  128
#define THREADS 256
#define CHUNK_FLOATS (KC * N_TILE)        // 8192 floats = 32 KB per buffer

typedef unsigned long long ull;

// ---------- packed fp32x2 helpers (FFMA2: ptxas never emits these from C++) ----------
__device__ __forceinline__ ull ffma2(ull a, ull b, ull c) {
    ull d;
    asm("fma.rn.f32x2 %0, %1, %2, %3;" : "=l"(d) : "l"(a), "l"(b), "l"(c));
    return d;
}
__device__ __forceinline__ ull splat2(float a) {
    ull d;
    asm("mov.b64 %0, {%1, %1};" : "=l"(d) : "f"(a));
    return d;
}
__device__ __forceinline__ float2 unpack2(ull v) {
    float2 r;
    asm("mov.b64 {%0, %1}, %2;" : "=f"(r.x), "=f"(r.y) : "l"(v));
    return r;
}
__device__ __forceinline__ void lds128(ull& lo, ull& hi, uint32_t addr) {
    asm("ld.shared.v2.u64 {%0, %1}, [%2];" : "=l"(lo), "=l"(hi) : "r"(addr));
}
__device__ __forceinline__ void cp_async16(uint32_t dst_smem, const void* src) {
    asm volatile("cp.async.cg.shared.global [%0], [%1], 16;" :: "r"(dst_smem), "l"(src) : "memory");
}

__global__ void __launch_bounds__(THREADS, 2)
fourier_kan_kernel(const float* __restrict__ x,
                   const float* __restrict__ fc,   // [IN_DIM,NH,2,OUT_DIM] == [K=32768,N=512]
                   const float* __restrict__ bias,
                   float*       __restrict__ out)
{
    extern __shared__ float Bs[];       // [2][KC][N_TILE]  = 64 KB dynamic

    const int tid = threadIdx.x;
    const int tx  = tid & 15;           // 0..15 -> cols {4tx..4tx+3} and {64+4tx..64+4tx+3}
    const int ty  = tid >> 4;           // 0..15 -> 4 batch rows each
    const int n0  = blockIdx.x * N_TILE;
    const int m0  = blockIdx.y * M_TILE;

    const uint32_t smem_u32 = (uint32_t)__cvta_generic_to_shared(Bs);

    // cp.async cooperative mapping: 2048 float4 per chunk, 8 per thread
    const int wwid  = tid >> 5;         // 0..7  -> base k-row
    const int wlane = tid & 31;         // 0..31 -> float4 column
    const uint32_t st_base = smem_u32 + (uint32_t)((wwid * N_TILE + wlane * 4) * 4);

    // conflict-free LDS base: lane tx reads 16 consecutive bytes at tx*16
    const uint32_t ld_base = smem_u32 + (uint32_t)(tx * 16);

    ull acc[4][4];
    #pragma unroll
    for (int i = 0; i < 4; ++i)
        #pragma unroll
        for (int j = 0; j < 4; ++j) acc[i][j] = 0ull;

    const float* xbase = x + (size_t)(m0 + ty * 4) * IN_DIM;

    // ---- prologue: async-load chunk 0 into buffer 0 ----
    {
        const float* src = fc + (size_t)wwid * OUT_DIM + n0 + wlane * 4;
        #pragma unroll
        for (int j = 0; j < 8; ++j)
            cp_async16(st_base + (uint32_t)(j * 8 * N_TILE * 4), src + (size_t)j * 8 * OUT_DIM);
        asm volatile("cp.async.commit_group;" ::: "memory");
    }

    for (int ci = 0; ci < IN_DIM; ++ci) {
        const int buf = ci & 1;

        // x values for this thread's 4 rows (L1-resident after first chunk)
        float xv[4];
        #pragma unroll
        for (int r = 0; r < 4; ++r) xv[r] = __ldg(&xbase[(size_t)r * IN_DIM + ci]);

        __syncthreads();   // everyone done reading buf^1 before we overwrite it

        if (ci + 1 < IN_DIM) {
            const float* src = fc + ((size_t)(ci + 1) * KC + wwid) * OUT_DIM + n0 + wlane * 4;
            const uint32_t dst = st_base + (uint32_t)((buf ^ 1) * CHUNK_FLOATS * 4);
            #pragma unroll
            for (int j = 0; j < 8; ++j)
                cp_async16(dst + (uint32_t)(j * 8 * N_TILE * 4), src + (size_t)j * 8 * OUT_DIM);
            asm volatile("cp.async.commit_group;" ::: "memory");
            asm volatile("cp.async.wait_group 1;" ::: "memory");   // chunk ci is ready
        } else {
            asm volatile("cp.async.wait_group 0;" ::: "memory");
        }

        // trig seeds: harmonic 1 via __sincosf, harmonic 2 via double angle
        float ca[4], sa[4], cb[4], sb[4], tt[4];
        #pragma unroll
        for (int r = 0; r < 4; ++r) {
            __sincosf(xv[r], &sa[r], &ca[r]);
            tt[r] = 2.0f * ca[r];
            cb[r] = __fmaf_rn(tt[r], ca[r], -1.0f);   // cos 2x
            sb[r] = tt[r] * sa[r];                    // sin 2x
        }

        __syncthreads();   // chunk ci visible to all threads

        const uint32_t B0 = ld_base + (uint32_t)(buf * CHUNK_FLOATS * 4);

        // one k-step: 2 conflict-free LDS.128 + 4 splats + 16 FFMA2
        #define KSTEP(krow, av)                                                        \
        {                                                                              \
            ull bq0, bq1, bq2, bq3;                                                    \
            lds128(bq0, bq1, B0 + (uint32_t)((krow) * N_TILE * 4));                    \
            lds128(bq2, bq3, B0 + (uint32_t)((krow) * N_TILE * 4 + 256));              \
            _Pragma("unroll")                                                          \
            for (int r = 0; r < 4; ++r) {                                              \
                ull aq = splat2((av)[r]);                                              \
                acc[r][0] = ffma2(aq, bq0, acc[r][0]);                                 \
                acc[r][1] = ffma2(aq, bq1, acc[r][1]);                                 \
                acc[r][2] = ffma2(aq, bq2, acc[r][2]);                                 \
                acc[r][3] = ffma2(aq, bq3, acc[r][3]);                                 \
            }                                                                          \
        }

        #pragma unroll
        for (int g = 0; g < NH; g += 2) {
            if (g) {   // advance a := harmonic g+1 (Chebyshev; neg folds into FFMA)
                #pragma unroll
                for (int r = 0; r < 4; ++r) {
                    ca[r] = __fmaf_rn(tt[r], cb[r], -ca[r]);
                    sa[r] = __fmaf_rn(tt[r], sb[r], -sa[r]);
                }
            }
            KSTEP(2 * g,     ca)   // cos((g+1)x)
            KSTEP(2 * g + 1, sa)   // sin((g+1)x)
            if (g) {   // advance b := harmonic g+2
                #pragma unroll
                for (int r = 0; r < 4; ++r) {
                    cb[r] = __fmaf_rn(tt[r], ca[r], -cb[r]);
                    sb[r] = __fmaf_rn(tt[r], sa[r], -sb[r]);
                }
            }
            KSTEP(2 * g + 2, cb)   // cos((g+2)x)
            KSTEP(2 * g + 3, sb)   // sin((g+2)x)
        }
        #undef KSTEP
    }

    // ---- epilogue: add bias, store 4 rows x (two float4 groups) ----
    // columns: n0 + 4tx + {0..3}  and  n0 + 64 + 4tx + {0..3}
    float bias_r[8];
    #pragma unroll
    for (int j = 0; j < 4; ++j) {
        bias_r[j]     = bias[n0 + 4 * tx + j];
        bias_r[4 + j] = bias[n0 + 64 + 4 * tx + j];
    }

    #pragma unroll
    for (int mi = 0; mi < 4; ++mi) {
        const int m = m0 + ty * 4 + mi;
        float* op = out + (size_t)m * OUT_DIM + n0 + 4 * tx;
        float2 v0 = unpack2(acc[mi][0]);
        float2 v1 = unpack2(acc[mi][1]);
        float2 v2 = unpack2(acc[mi][2]);
        float2 v3 = unpack2(acc[mi][3]);
        float4 o0, o1;
        o0.x = v0.x + bias_r[0]; o0.y = v0.y + bias_r[1];
        o0.z = v1.x + bias_r[2]; o0.w = v1.y + bias_r[3];
        o1.x = v2.x + bias_r[4]; o1.y = v2.y + bias_r[5];
        o1.z = v3.x + bias_r[6]; o1.w = v3.y + bias_r[7];
        *reinterpret_cast<float4*>(op)      = o0;
        *reinterpret_cast<float4*>(op + 64) = o1;
    }
}

extern "C" void kernel_launch(void* const* d_in, const int* in_sizes, int n_in,
                              void* d_out, int out_size) {
    const float* x    = (const float*)d_in[0];   // [4096, 512]
    const float* fc   = (const float*)d_in[1];   // [512, 32, 2, 512]
    const float* bias = (const float*)d_in[2];   // [512]
    float* out        = (float*)d_out;           // [4096, 512]

    const int smem = 2 * CHUNK_FLOATS * sizeof(float);   // 64 KB
    cudaFuncSetAttribute(fourier_kan_kernel,
                         cudaFuncAttributeMaxDynamicSharedMemorySize, smem);

    dim3 grid(OUT_DIM / N_TILE, BATCH / M_TILE);         // (4, 64) = 256 CTAs
    fourier_kan_kernel<<<grid, THREADS, smem>>>(x, fc, bias, out);
}

// round 13
// speedup vs baseline: 1.6663x; 1.0033x over previous
#include <cuda_runtime.h>
#include <cstdint>

// Problem constants (fixed by the reference)
#define BATCH   4096
#define IN_DIM  512
#define OUT_DIM 512
#define NH      32
#define KC      64            // K-chunk = one input dim: 32 harmonics x {cos,sin}

#define M_TILE  64
#define N_TILE  128
#define THREADS 256
#define CHUNK_FLOATS (KC * N_TILE)        // 8192 floats = 32 KB per buffer

typedef unsigned long long ull;

// ---------- packed fp32x2 helpers (FFMA2: ptxas never emits these from C++) ----------
__device__ __forceinline__ ull ffma2(ull a, ull b, ull c) {
    ull d;
    asm("fma.rn.f32x2 %0, %1, %2, %3;" : "=l"(d) : "l"(a), "l"(b), "l"(c));
    return d;
}
__device__ __forceinline__ ull splat2(float a) {
    ull d;
    asm("mov.b64 %0, {%1, %1};" : "=l"(d) : "f"(a));
    return d;
}
__device__ __forceinline__ float2 unpack2(ull v) {
    float2 r;
    asm("mov.b64 {%0, %1}, %2;" : "=f"(r.x), "=f"(r.y) : "l"(v));
    return r;
}
__device__ __forceinline__ void lds128(ull& lo, ull& hi, uint32_t addr) {
    asm("ld.shared.v2.u64 {%0, %1}, [%2];" : "=l"(lo), "=l"(hi) : "r"(addr));
}
__device__ __forceinline__ void cp_async16(uint32_t dst_smem, const void* src) {
    asm volatile("cp.async.cg.shared.global [%0], [%1], 16;" :: "r"(dst_smem), "l"(src) : "memory");
}

__global__ void __launch_bounds__(THREADS, 2)
fourier_kan_kernel(const float* __restrict__ x,
                   const float* __restrict__ fc,   // [IN_DIM,NH,2,OUT_DIM] == [K=32768,N=512]
                   const float* __restrict__ bias,
                   float*       __restrict__ out)
{
    extern __shared__ float Bs[];       // [2][KC][N_TILE]  = 64 KB dynamic

    const int tid = threadIdx.x;
    const int tx  = tid & 15;           // 0..15 -> cols {4tx..4tx+3} and {64+4tx..64+4tx+3}
    const int ty  = tid >> 4;           // 0..15 -> 4 batch rows each
    const int n0  = blockIdx.x * N_TILE;
    const int m0  = blockIdx.y * M_TILE;

    const uint32_t smem_u32 = (uint32_t)__cvta_generic_to_shared(Bs);

    // cp.async cooperative mapping: 2048 float4 per chunk, 8 per thread
    const int wwid  = tid >> 5;         // 0..7  -> base k-row
    const int wlane = tid & 31;         // 0..31 -> float4 column
    const uint32_t st_base = smem_u32 + (uint32_t)((wwid * N_TILE + wlane * 4) * 4);

    // conflict-free LDS base: lane tx reads 16 consecutive bytes at tx*16
    const uint32_t ld_base = smem_u32 + (uint32_t)(tx * 16);

    ull acc[4][4];
    #pragma unroll
    for (int i = 0; i < 4; ++i)
        #pragma unroll
        for (int j = 0; j < 4; ++j) acc[i][j] = 0ull;

    const float* xbase = x + (size_t)(m0 + ty * 4) * IN_DIM;

    // ---- prologue: async-load chunk 0 into buffer 0 ----
    {
        const float* src = fc + (size_t)wwid * OUT_DIM + n0 + wlane * 4;
        #pragma unroll
        for (int j = 0; j < 8; ++j)
            cp_async16(st_base + (uint32_t)(j * 8 * N_TILE * 4), src + (size_t)j * 8 * OUT_DIM);
        asm volatile("cp.async.commit_group;" ::: "memory");
    }

    for (int ci = 0; ci < IN_DIM; ++ci) {
        const int buf = ci & 1;

        // x values for this thread's 4 rows (L1-resident after first chunk)
        float xv[4];
        #pragma unroll
        for (int r = 0; r < 4; ++r) xv[r] = __ldg(&xbase[(size_t)r * IN_DIM + ci]);

        __syncthreads();   // everyone done reading buf^1 before we overwrite it

        if (ci + 1 < IN_DIM) {
            const float* src = fc + ((size_t)(ci + 1) * KC + wwid) * OUT_DIM + n0 + wlane * 4;
            const uint32_t dst = st_base + (uint32_t)((buf ^ 1) * CHUNK_FLOATS * 4);
            #pragma unroll
            for (int j = 0; j < 8; ++j)
                cp_async16(dst + (uint32_t)(j * 8 * N_TILE * 4), src + (size_t)j * 8 * OUT_DIM);
            asm volatile("cp.async.commit_group;" ::: "memory");
            asm volatile("cp.async.wait_group 1;" ::: "memory");   // chunk ci is ready
        } else {
            asm volatile("cp.async.wait_group 0;" ::: "memory");
        }

        // trig seeds: harmonic 1 via __sincosf, harmonic 2 via double angle
        float ca[4], sa[4], cb[4], sb[4], tt[4];
        #pragma unroll
        for (int r = 0; r < 4; ++r) {
            __sincosf(xv[r], &sa[r], &ca[r]);
            tt[r] = 2.0f * ca[r];
            cb[r] = __fmaf_rn(tt[r], ca[r], -1.0f);   // cos 2x
            sb[r] = tt[r] * sa[r];                    // sin 2x
        }

        __syncthreads();   // chunk ci visible to all threads

        const uint32_t B0 = ld_base + (uint32_t)(buf * CHUNK_FLOATS * 4);

        // one k-step: 2 conflict-free LDS.128 + 4 splats + 16 FFMA2
        #define KSTEP(krow, av)                                                        \
        {                                                                              \
            ull bq0, bq1, bq2, bq3;                                                    \
            lds128(bq0, bq1, B0 + (uint32_t)((krow) * N_TILE * 4));                    \
            lds128(bq2, bq3, B0 + (uint32_t)((krow) * N_TILE * 4 + 256));              \
            _Pragma("unroll")                                                          \
            for (int r = 0; r < 4; ++r) {                                              \
                ull aq = splat2((av)[r]);                                              \
                acc[r][0] = ffma2(aq, bq0, acc[r][0]);                                 \
                acc[r][1] = ffma2(aq, bq1, acc[r][1]);                                 \
                acc[r][2] = ffma2(aq, bq2, acc[r][2]);                                 \
                acc[r][3] = ffma2(aq, bq3, acc[r][3]);                                 \
            }                                                                          \
        }

        #pragma unroll
        for (int g = 0; g < NH; g += 2) {
            if (g) {   // advance a := harmonic g+1 (Chebyshev; neg folds into FFMA)
                #pragma unroll
                for (int r = 0; r < 4; ++r) {
                    ca[r] = __fmaf_rn(tt[r], cb[r], -ca[r]);
                    sa[r] = __fmaf_rn(tt[r], sb[r], -sa[r]);
                }
            }
            KSTEP(2 * g,     ca)   // cos((g+1)x)
            KSTEP(2 * g + 1, sa)   // sin((g+1)x)
            if (g) {   // advance b := harmonic g+2
                #pragma unroll
                for (int r = 0; r < 4; ++r) {
                    cb[r] = __fmaf_rn(tt[r], ca[r], -cb[r]);
                    sb[r] = __fmaf_rn(tt[r], sa[r], -sb[r]);
                }
            }
            KSTEP(2 * g + 2, cb)   // cos((g+2)x)
            KSTEP(2 * g + 3, sb)   // sin((g+2)x)
        }
        #undef KSTEP
    }

    // ---- epilogue: add bias, store 4 rows x (two float4 groups) ----
    // columns: n0 + 4tx + {0..3}  and  n0 + 64 + 4tx + {0..3}
    float bias_r[8];
    #pragma unroll
    for (int j = 0; j < 4; ++j) {
        bias_r[j]     = bias[n0 + 4 * tx + j];
        bias_r[4 + j] = bias[n0 + 64 + 4 * tx + j];
    }

    #pragma unroll
    for (int mi = 0; mi < 4; ++mi) {
        const int m = m0 + ty * 4 + mi;
        float* op = out + (size_t)m * OUT_DIM + n0 + 4 * tx;
        float2 v0 = unpack2(acc[mi][0]);
        float2 v1 = unpack2(acc[mi][1]);
        float2 v2 = unpack2(acc[mi][2]);
        float2 v3 = unpack2(acc[mi][3]);
        float4 o0, o1;
        o0.x = v0.x + bias_r[0]; o0.y = v0.y + bias_r[1];
        o0.z = v1.x + bias_r[2]; o0.w = v1.y + bias_r[3];
        o1.x = v2.x + bias_r[4]; o1.y = v2.y + bias_r[5];
        o1.z = v3.x + bias_r[6]; o1.w = v3.y + bias_r[7];
        *reinterpret_cast<float4*>(op)      = o0;
        *reinterpret_cast<float4*>(op + 64) = o1;
    }
}

extern "C" void kernel_launch(void* const* d_in, const int* in_sizes, int n_in,
                              void* d_out, int out_size) {
    const float* x    = (const float*)d_in[0];   // [4096, 512]
    const float* fc   = (const float*)d_in[1];   // [512, 32, 2, 512]
    const float* bias = (const float*)d_in[2];   // [512]
    float* out        = (float*)d_out;           // [4096, 512]

    const int smem = 2 * CHUNK_FLOATS * sizeof(float);   // 64 KB
    cudaFuncSetAttribute(fourier_kan_kernel,
                         cudaFuncAttributeMaxDynamicSharedMemorySize, smem);

    dim3 grid(OUT_DIM / N_TILE, BATCH / M_TILE);         // (4, 64) = 256 CTAs
    fourier_kan_kernel<<<grid, THREADS, smem>>>(x, fc, bias, out);
}

// round 16
// speedup vs baseline: 1.6670x; 1.0005x over previous
#include <cuda_runtime.h>
#include <cstdint>

// Problem constants (fixed by the reference)
#define BATCH   4096
#define IN_DIM  512
#define OUT_DIM 512
#define NH      32
#define KC      64            // K-chunk = one input dim: 32 harmonics x {cos,sin}

#define M_TILE  64
#define N_TILE  128
#define THREADS 256
#define CHUNK_FLOATS (KC * N_TILE)        // 8192 floats = 32 KB per buffer

typedef unsigned long long ull;

// ---------- packed fp32x2 helpers (FFMA2: ptxas never emits these from C++) ----------
__device__ __forceinline__ ull ffma2(ull a, ull b, ull c) {
    ull d;
    asm("fma.rn.f32x2 %0, %1, %2, %3;" : "=l"(d) : "l"(a), "l"(b), "l"(c));
    return d;
}
__device__ __forceinline__ ull splat2(float a) {
    ull d;
    asm("mov.b64 %0, {%1, %1};" : "=l"(d) : "f"(a));
    return d;
}
__device__ __forceinline__ float2 unpack2(ull v) {
    float2 r;
    asm("mov.b64 {%0, %1}, %2;" : "=f"(r.x), "=f"(r.y) : "l"(v));
    return r;
}
__device__ __forceinline__ void lds128(ull& lo, ull& hi, uint32_t addr) {
    asm("ld.shared.v2.u64 {%0, %1}, [%2];" : "=l"(lo), "=l"(hi) : "r"(addr));
}
__device__ __forceinline__ void cp_async16(uint32_t dst_smem, const void* src) {
    asm volatile("cp.async.cg.shared.global [%0], [%1], 16;" :: "r"(dst_smem), "l"(src) : "memory");
}

__global__ void __launch_bounds__(THREADS, 2)
fourier_kan_kernel(const float* __restrict__ x,
                   const float* __restrict__ fc,   // [IN_DIM,NH,2,OUT_DIM] == [K=32768,N=512]
                   const float* __restrict__ bias,
                   float*       __restrict__ out)
{
    extern __shared__ float Bs[];       // [2][KC][N_TILE]  = 64 KB dynamic

    const int tid = threadIdx.x;
    const int tx  = tid & 15;           // 0..15 -> cols {4tx..4tx+3} and {64+4tx..64+4tx+3}
    const int ty  = tid >> 4;           // 0..15 -> 4 batch rows each
    const int n0  = blockIdx.x * N_TILE;
    const int m0  = blockIdx.y * M_TILE;

    const uint32_t smem_u32 = (uint32_t)__cvta_generic_to_shared(Bs);

    // cp.async cooperative mapping: 2048 float4 per chunk, 8 per thread
    const int wwid  = tid >> 5;         // 0..7  -> base k-row
    const int wlane = tid & 31;         // 0..31 -> float4 column
    const uint32_t st_base = smem_u32 + (uint32_t)((wwid * N_TILE + wlane * 4) * 4);

    // conflict-free LDS base: lane tx reads 16 consecutive bytes at tx*16
    const uint32_t ld_base = smem_u32 + (uint32_t)(tx * 16);

    ull acc[4][4];
    #pragma unroll
    for (int i = 0; i < 4; ++i)
        #pragma unroll
        for (int j = 0; j < 4; ++j) acc[i][j] = 0ull;

    const float* xbase = x + (size_t)(m0 + ty * 4) * IN_DIM;

    // ---- prologue: async-load chunk 0 into buffer 0 ----
    {
        const float* src = fc + (size_t)wwid * OUT_DIM + n0 + wlane * 4;
        #pragma unroll
        for (int j = 0; j < 8; ++j)
            cp_async16(st_base + (uint32_t)(j * 8 * N_TILE * 4), src + (size_t)j * 8 * OUT_DIM);
        asm volatile("cp.async.commit_group;" ::: "memory");
    }

    for (int ci = 0; ci < IN_DIM; ++ci) {
        const int buf = ci & 1;

        // x values for this thread's 4 rows (L1-resident after first chunk)
        float xv[4];
        #pragma unroll
        for (int r = 0; r < 4; ++r) xv[r] = __ldg(&xbase[(size_t)r * IN_DIM + ci]);

        __syncthreads();   // everyone done reading buf^1 before we overwrite it

        if (ci + 1 < IN_DIM) {
            const float* src = fc + ((size_t)(ci + 1) * KC + wwid) * OUT_DIM + n0 + wlane * 4;
            const uint32_t dst = st_base + (uint32_t)((buf ^ 1) * CHUNK_FLOATS * 4);
            #pragma unroll
            for (int j = 0; j < 8; ++j)
                cp_async16(dst + (uint32_t)(j * 8 * N_TILE * 4), src + (size_t)j * 8 * OUT_DIM);
            asm volatile("cp.async.commit_group;" ::: "memory");
            asm volatile("cp.async.wait_group 1;" ::: "memory");   // chunk ci is ready
        } else {
            asm volatile("cp.async.wait_group 0;" ::: "memory");
        }

        // trig seeds: harmonic 1 via __sincosf, harmonic 2 via double angle
        float ca[4], sa[4], cb[4], sb[4], tt[4];
        #pragma unroll
        for (int r = 0; r < 4; ++r) {
            __sincosf(xv[r], &sa[r], &ca[r]);
            tt[r] = 2.0f * ca[r];
            cb[r] = __fmaf_rn(tt[r], ca[r], -1.0f);   // cos 2x
            sb[r] = tt[r] * sa[r];                    // sin 2x
        }

        __syncthreads();   // chunk ci visible to all threads

        const uint32_t B0 = ld_base + (uint32_t)(buf * CHUNK_FLOATS * 4);

        // one k-step: 2 conflict-free LDS.128 + 4 splats + 16 FFMA2
        #define KSTEP(krow, av)                                                        \
        {                                                                              \
            ull bq0, bq1, bq2, bq3;                                                    \
            lds128(bq0, bq1, B0 + (uint32_t)((krow) * N_TILE * 4));                    \
            lds128(bq2, bq3, B0 + (uint32_t)((krow) * N_TILE * 4 + 256));              \
            _Pragma("unroll")                                                          \
            for (int r = 0; r < 4; ++r) {                                              \
                ull aq = splat2((av)[r]);                                              \
                acc[r][0] = ffma2(aq, bq0, acc[r][0]);                                 \
                acc[r][1] = ffma2(aq, bq1, acc[r][1]);                                 \
                acc[r][2] = ffma2(aq, bq2, acc[r][2]);                                 \
                acc[r][3] = ffma2(aq, bq3, acc[r][3]);                                 \
            }                                                                          \
        }

        #pragma unroll
        for (int g = 0; g < NH; g += 2) {
            if (g) {   // advance a := harmonic g+1 (Chebyshev; neg folds into FFMA)
                #pragma unroll
                for (int r = 0; r < 4; ++r) {
                    ca[r] = __fmaf_rn(tt[r], cb[r], -ca[r]);
                    sa[r] = __fmaf_rn(tt[r], sb[r], -sa[r]);
                }
            }
            KSTEP(2 * g,     ca)   // cos((g+1)x)
            KSTEP(2 * g + 1, sa)   // sin((g+1)x)
            if (g) {   // advance b := harmonic g+2
                #pragma unroll
                for (int r = 0; r < 4; ++r) {
                    cb[r] = __fmaf_rn(tt[r], ca[r], -cb[r]);
                    sb[r] = __fmaf_rn(tt[r], sa[r], -sb[r]);
                }
            }
            KSTEP(2 * g + 2, cb)   // cos((g+2)x)
            KSTEP(2 * g + 3, sb)   // sin((g+2)x)
        }
        #undef KSTEP
    }

    // ---- epilogue: add bias, store 4 rows x (two float4 groups) ----
    // columns: n0 + 4tx + {0..3}  and  n0 + 64 + 4tx + {0..3}
    float bias_r[8];
    #pragma unroll
    for (int j = 0; j < 4; ++j) {
        bias_r[j]     = bias[n0 + 4 * tx + j];
        bias_r[4 + j] = bias[n0 + 64 + 4 * tx + j];
    }

    #pragma unroll
    for (int mi = 0; mi < 4; ++mi) {
        const int m = m0 + ty * 4 + mi;
        float* op = out + (size_t)m * OUT_DIM + n0 + 4 * tx;
        float2 v0 = unpack2(acc[mi][0]);
        float2 v1 = unpack2(acc[mi][1]);
        float2 v2 = unpack2(acc[mi][2]);
        float2 v3 = unpack2(acc[mi][3]);
        float4 o0, o1;
        o0.x = v0.x + bias_r[0]; o0.y = v0.y + bias_r[1];
        o0.z = v1.x + bias_r[2]; o0.w = v1.y + bias_r[3];
        o1.x = v2.x + bias_r[4]; o1.y = v2.y + bias_r[5];
        o1.z = v3.x + bias_r[6]; o1.w = v3.y + bias_r[7];
        *reinterpret_cast<float4*>(op)      = o0;
        *reinterpret_cast<float4*>(op + 64) = o1;
    }
}

extern "C" void kernel_launch(void* const* d_in, const int* in_sizes, int n_in,
                              void* d_out, int out_size) {
    const float* x    = (const float*)d_in[0];   // [4096, 512]
    const float* fc   = (const float*)d_in[1];   // [512, 32, 2, 512]
    const float* bias = (const float*)d_in[2];   // [512]
    float* out        = (float*)d_out;           // [4096, 512]

    const int smem = 2 * CHUNK_FLOATS * sizeof(float);   // 64 KB
    cudaFuncSetAttribute(fourier_kan_kernel,
                         cudaFuncAttributeMaxDynamicSharedMemorySize, smem);

    dim3 grid(OUT_DIM / N_TILE, BATCH / M_TILE);         // (4, 64) = 256 CTAs
    fourier_kan_kernel<<<grid, THREADS, smem>>>(x, fc, bias, out);
}